// round 1
// baseline (speedup 1.0000x reference)
#include <cuda_runtime.h>
#include <math.h>

// Problem constants
#define B_  2
#define N_  2048
#define D_  1024
#define H_  16
#define DH_ 64
#define E3_ 192           // 3*DH per head, chunk order (k,q,v)
#define J3_ 3072          // H * 3*DH

// Scratch (device globals: allowed; no runtime allocation)
__device__ float g_q [(size_t)B_*H_*N_*DH_];
__device__ float g_k [(size_t)B_*H_*N_*DH_];
__device__ float g_v [(size_t)B_*H_*N_*DH_];
__device__ float g_sa[(size_t)B_*N_*D_];
__device__ float g_attn[(size_t)B_*H_*N_*N_];  // 512 MB fallback if attn not in d_out

// ---------------------------------------------------------------------------
// Kernel 1: QKV projection.  C[m, j] = sum_d x[m,d] * Wqkv[h, d, e] + bqkv[h,e]
//   m in [0,4096) = b*N+n ; j in [0,3072), h=j/192, e=j%192.
//   Scatter: e<64 -> k, e<128 -> q, else v, stored [B,H,N,DH].
// 64x64 tile, 256 threads, 4x4 micro-tile, k-tile 32.
// ---------------------------------------------------------------------------
__global__ __launch_bounds__(256) void qkv_gemm(
    const float* __restrict__ x, const float* __restrict__ W,
    const float* __restrict__ bias,
    float* __restrict__ qo, float* __restrict__ ko, float* __restrict__ vo)
{
    const int m0 = blockIdx.x * 64;
    const int j0 = blockIdx.y * 64;           // 192 = 3*64 -> tile never crosses head
    const int h  = j0 / E3_;
    const int e0 = j0 % E3_;
    const int tid = threadIdx.x;
    const int ty = tid >> 4, tx = tid & 15;

    __shared__ float As[64][33];
    __shared__ float Bs[64][33];

    float acc[4][4] = {};

    for (int k0 = 0; k0 < D_; k0 += 32) {
        #pragma unroll
        for (int i = 0; i < 8; i++) {
            int idx = tid + i * 256;          // 0..2047
            int r = idx >> 5, c = idx & 31;   // c contiguous per tid -> coalesced
            As[r][c] = x[(size_t)(m0 + r) * D_ + k0 + c];
        }
        #pragma unroll
        for (int i = 0; i < 8; i++) {
            int idx = tid + i * 256;
            int c = idx >> 6, jc = idx & 63;  // jc contiguous per tid -> coalesced
            Bs[jc][c] = W[((size_t)h * D_ + k0 + c) * E3_ + e0 + jc];
        }
        __syncthreads();
        #pragma unroll 8
        for (int c = 0; c < 32; c++) {
            float a[4], b[4];
            #pragma unroll
            for (int i = 0; i < 4; i++) a[i] = As[ty * 4 + i][c];
            #pragma unroll
            for (int j = 0; j < 4; j++) b[j] = Bs[tx * 4 + j][c];
            #pragma unroll
            for (int i = 0; i < 4; i++)
                #pragma unroll
                for (int j = 0; j < 4; j++)
                    acc[i][j] += a[i] * b[j];
        }
        __syncthreads();
    }

    #pragma unroll
    for (int i = 0; i < 4; i++) {
        int m = m0 + ty * 4 + i;
        int n = m & (N_ - 1);
        int b = m >> 11;
        size_t base = ((size_t)(b * H_ + h) * N_ + n) * DH_;
        #pragma unroll
        for (int j = 0; j < 4; j++) {
            int e = e0 + tx * 4 + j;
            float val = acc[i][j] + bias[h * E3_ + e];
            if (e < DH_)            ko[base + e] = val;
            else if (e < 2 * DH_)   qo[base + e - DH_] = val;
            else                    vo[base + e - 2 * DH_] = val;
        }
    }
}

// ---------------------------------------------------------------------------
// Kernel 2: scores[b,h,q,k] = (q . k) / 8  for k-tiles <= q-tile (causal).
// 64x64 tile, 256 threads, 4x4 micro-tile, full DH=64 in smem.
// ---------------------------------------------------------------------------
__global__ __launch_bounds__(256) void scores_kernel(
    const float* __restrict__ q, const float* __restrict__ k,
    float* __restrict__ attn)
{
    const int qt = blockIdx.x, kt = blockIdx.y, bh = blockIdx.z;
    if (kt > qt) return;

    __shared__ float qs[64][65];
    __shared__ float ks[64][65];

    const int tid = threadIdx.x;
    const float* qb = q + ((size_t)bh * N_ + qt * 64) * DH_;
    const float* kb = k + ((size_t)bh * N_ + kt * 64) * DH_;

    #pragma unroll
    for (int i = 0; i < 16; i++) {
        int idx = tid + i * 256;
        int r = idx >> 6, c = idx & 63;
        qs[r][c] = qb[(size_t)r * DH_ + c];
        ks[r][c] = kb[(size_t)r * DH_ + c];
    }
    __syncthreads();

    const int ty = tid >> 4, tx = tid & 15;
    float acc[4][4] = {};
    #pragma unroll 8
    for (int d = 0; d < DH_; d++) {
        float a[4], b[4];
        #pragma unroll
        for (int i = 0; i < 4; i++) a[i] = qs[ty * 4 + i][d];
        #pragma unroll
        for (int j = 0; j < 4; j++) b[j] = ks[tx * 4 + j][d];
        #pragma unroll
        for (int i = 0; i < 4; i++)
            #pragma unroll
            for (int j = 0; j < 4; j++)
                acc[i][j] += a[i] * b[j];
    }

    float* abase = attn + (size_t)bh * N_ * N_;
    #pragma unroll
    for (int i = 0; i < 4; i++) {
        int qi = qt * 64 + ty * 4 + i;
        #pragma unroll
        for (int j = 0; j < 4; j++) {
            int ki = kt * 64 + tx * 4 + j;
            // masked (ki>qi) positions inside the diagonal tile are never read
            abase[(size_t)qi * N_ + ki] = acc[i][j] * 0.125f;
        }
    }
}

// ---------------------------------------------------------------------------
// Kernel 3: row softmax, in place on attn. One block per (b,h,q) row.
// Valid length = q+1; writes zeros for k>q (matches -inf softmax exactly).
// ---------------------------------------------------------------------------
__global__ __launch_bounds__(256) void softmax_kernel(float* __restrict__ attn)
{
    const size_t row = blockIdx.x;
    const int qpos = blockIdx.x & (N_ - 1);
    float* s = attn + row * N_;
    const int tid = threadIdx.x;
    __shared__ float red[256];

    float m = -1e30f;
    for (int i = tid; i <= qpos; i += 256) m = fmaxf(m, s[i]);
    red[tid] = m; __syncthreads();
    #pragma unroll
    for (int o = 128; o > 0; o >>= 1) {
        if (tid < o) red[tid] = fmaxf(red[tid], red[tid + o]);
        __syncthreads();
    }
    m = red[0]; __syncthreads();

    float sum = 0.f;
    for (int i = tid; i <= qpos; i += 256) sum += __expf(s[i] - m);
    red[tid] = sum; __syncthreads();
    #pragma unroll
    for (int o = 128; o > 0; o >>= 1) {
        if (tid < o) red[tid] += red[tid + o];
        __syncthreads();
    }
    const float inv = 1.0f / red[0];

    for (int i = tid; i < N_; i += 256)
        s[i] = (i <= qpos) ? __expf(s[i] - m) * inv : 0.f;
}

// ---------------------------------------------------------------------------
// Kernel 4: sa = attn @ v, per (b,h). Causal: loop only k-tiles <= q-tile
// (attn is exactly 0 above the diagonal inside the diagonal tile).
// Output stored [B, N, H*DH] (heads concatenated) to feed the projection.
// ---------------------------------------------------------------------------
__global__ __launch_bounds__(256) void sa_kernel(
    const float* __restrict__ attn, const float* __restrict__ v,
    float* __restrict__ sa)
{
    const int qt = blockIdx.x, bh = blockIdx.y;
    __shared__ float as[64][65];
    __shared__ float vs[64][65];

    const int tid = threadIdx.x;
    const int ty = tid >> 4, tx = tid & 15;
    float acc[4][4] = {};

    const float* abase = attn + ((size_t)bh * N_ + qt * 64) * N_;
    const float* vbase = v + (size_t)bh * N_ * DH_;

    for (int kt = 0; kt <= qt; kt++) {
        #pragma unroll
        for (int i = 0; i < 16; i++) {
            int idx = tid + i * 256;
            int r = idx >> 6, c = idx & 63;
            as[r][c] = abase[(size_t)r * N_ + kt * 64 + c];
            vs[r][c] = vbase[(size_t)(kt * 64 + r) * DH_ + c];
        }
        __syncthreads();
        #pragma unroll 8
        for (int d = 0; d < 64; d++) {
            float a[4], b[4];
            #pragma unroll
            for (int i = 0; i < 4; i++) a[i] = as[ty * 4 + i][d];
            #pragma unroll
            for (int j = 0; j < 4; j++) b[j] = vs[d][tx * 4 + j];
            #pragma unroll
            for (int i = 0; i < 4; i++)
                #pragma unroll
                for (int j = 0; j < 4; j++)
                    acc[i][j] += a[i] * b[j];
        }
        __syncthreads();
    }

    const int b = bh >> 4, h = bh & 15;
    #pragma unroll
    for (int i = 0; i < 4; i++) {
        int n = qt * 64 + ty * 4 + i;
        #pragma unroll
        for (int j = 0; j < 4; j++)
            sa[((size_t)b * N_ + n) * D_ + h * DH_ + tx * 4 + j] = acc[i][j];
    }
}

// ---------------------------------------------------------------------------
// Kernel 5: out = sa @ Wproj^T + bproj.  out[m,j] = sum_d sa[m,d]*Wproj[j,d]
// ---------------------------------------------------------------------------
__global__ __launch_bounds__(256) void proj_gemm(
    const float* __restrict__ sa, const float* __restrict__ W,
    const float* __restrict__ bias, float* __restrict__ out)
{
    const int m0 = blockIdx.x * 64;
    const int j0 = blockIdx.y * 64;
    const int tid = threadIdx.x;
    const int ty = tid >> 4, tx = tid & 15;

    __shared__ float As[64][33];
    __shared__ float Bs[64][33];
    float acc[4][4] = {};

    for (int k0 = 0; k0 < D_; k0 += 32) {
        #pragma unroll
        for (int i = 0; i < 8; i++) {
            int idx = tid + i * 256;
            int r = idx >> 5, c = idx & 31;
            As[r][c] = sa[(size_t)(m0 + r) * D_ + k0 + c];
            Bs[r][c] = W [(size_t)(j0 + r) * D_ + k0 + c];
        }
        __syncthreads();
        #pragma unroll 8
        for (int c = 0; c < 32; c++) {
            float a[4], b[4];
            #pragma unroll
            for (int i = 0; i < 4; i++) a[i] = As[ty * 4 + i][c];
            #pragma unroll
            for (int j = 0; j < 4; j++) b[j] = Bs[tx * 4 + j][c];
            #pragma unroll
            for (int i = 0; i < 4; i++)
                #pragma unroll
                for (int j = 0; j < 4; j++)
                    acc[i][j] += a[i] * b[j];
        }
        __syncthreads();
    }

    #pragma unroll
    for (int i = 0; i < 4; i++) {
        int m = m0 + ty * 4 + i;
        #pragma unroll
        for (int j = 0; j < 4; j++) {
            int jj = j0 + tx * 4 + j;
            out[(size_t)m * D_ + jj] = acc[i][j] + bias[jj];
        }
    }
}

// ---------------------------------------------------------------------------
extern "C" void kernel_launch(void* const* d_in, const int* in_sizes, int n_in,
                              void* d_out, int out_size)
{
    const float* x     = (const float*)d_in[0];
    const float* Wqkv  = (const float*)d_in[1];
    const float* bqkv  = (const float*)d_in[2];
    const float* Wproj = (const float*)d_in[3];
    const float* bproj = (const float*)d_in[4];
    float* out = (float*)d_out;

    const size_t OUT_ELEMS  = (size_t)B_ * N_ * D_;          // 4,194,304
    const size_t ATTN_ELEMS = (size_t)B_ * H_ * N_ * N_;     // 134,217,728

    float *qp, *kp, *vp, *sap, *attnp;
    cudaGetSymbolAddress((void**)&qp,  g_q);
    cudaGetSymbolAddress((void**)&kp,  g_k);
    cudaGetSymbolAddress((void**)&vp,  g_v);
    cudaGetSymbolAddress((void**)&sap, g_sa);
    cudaGetSymbolAddress((void**)&attnp, g_attn);

    if ((size_t)out_size >= OUT_ELEMS + ATTN_ELEMS)
        attnp = out + OUT_ELEMS;   // tuple output (out, attn) flattened

    // 1) QKV projection
    qkv_gemm<<<dim3(B_ * N_ / 64, J3_ / 64), 256>>>(x, Wqkv, bqkv, qp, kp, vp);
    // 2) causal scores
    scores_kernel<<<dim3(N_ / 64, N_ / 64, B_ * H_), 256>>>(qp, kp, attnp);
    // 3) row softmax (in place)
    softmax_kernel<<<B_ * H_ * N_, 256>>>(attnp);
    // 4) sa = attn @ v
    sa_kernel<<<dim3(N_ / 64, B_ * H_), 256>>>(attnp, vp, sap);
    // 5) output projection
    proj_gemm<<<dim3(B_ * N_ / 64, D_ / 64), 256>>>(sap, Wproj, bproj, out);
}

// round 3
// speedup vs baseline: 1.6843x; 1.6843x over previous
#include <cuda_runtime.h>
#include <cuda_bf16.h>
#include <math.h>
#include <stdint.h>

// Problem constants
#define B_  2
#define N_  2048
#define D_  1024
#define H_  16
#define DH_ 64
#define E3_ 192           // 3*DH per head, chunk order (k,q,v)
#define J3_ 3072          // H * 3*DH
#define M_  4096          // B*N

// ---------------------------------------------------------------------------
// Scratch (device globals: allowed; no runtime allocation)
// ---------------------------------------------------------------------------
__device__ float g_q [(size_t)B_*H_*N_*DH_];
__device__ float g_k [(size_t)B_*H_*N_*DH_];
__device__ float g_v [(size_t)B_*H_*N_*DH_];
__device__ float g_sa[(size_t)B_*N_*D_];
__device__ float g_attn[(size_t)B_*H_*N_*N_];  // fallback if attn not in d_out

// bf16 split buffers (hi/lo) for tensor-core GEMMs
__device__ __nv_bfloat16 g_xhi [(size_t)M_*D_];
__device__ __nv_bfloat16 g_xlo [(size_t)M_*D_];
__device__ __nv_bfloat16 g_wqhi[(size_t)J3_*D_];   // Wqkv transposed to [j, d]
__device__ __nv_bfloat16 g_wqlo[(size_t)J3_*D_];
__device__ __nv_bfloat16 g_wphi[(size_t)D_*D_];
__device__ __nv_bfloat16 g_wplo[(size_t)D_*D_];
__device__ __nv_bfloat16 g_sahi[(size_t)M_*D_];
__device__ __nv_bfloat16 g_salo[(size_t)M_*D_];

// ---------------------------------------------------------------------------
// mma.sync / ldmatrix helpers (base sm_103 features — NOT tcgen05/'a'-gated)
// ---------------------------------------------------------------------------
__device__ __forceinline__ uint32_t smem_u32(const void* p) {
    uint32_t a;
    asm("{ .reg .u64 t; cvta.to.shared.u64 t, %1; cvt.u32.u64 %0, t; }"
        : "=r"(a) : "l"(p));
    return a;
}

#define LDM4(r, addr)                                                         \
    asm volatile("ldmatrix.sync.aligned.m8n8.x4.shared.b16 {%0,%1,%2,%3}, [%4];" \
        : "=r"((r)[0]), "=r"((r)[1]), "=r"((r)[2]), "=r"((r)[3])              \
        : "r"(addr))

#define MMA_BF16(c, a, b0, b1)                                                \
    asm volatile("mma.sync.aligned.m16n8k16.row.col.f32.bf16.bf16.f32 "       \
        "{%0,%1,%2,%3}, {%4,%5,%6,%7}, {%8,%9}, {%0,%1,%2,%3};"               \
        : "+f"((c)[0]), "+f"((c)[1]), "+f"((c)[2]), "+f"((c)[3])              \
        : "r"((a)[0]), "r"((a)[1]), "r"((a)[2]), "r"((a)[3]), "r"(b0), "r"(b1))

// ---------------------------------------------------------------------------
// bf16 hi/lo split conversion kernels
// ---------------------------------------------------------------------------
__global__ __launch_bounds__(256) void split_kernel(
    const float* __restrict__ in, __nv_bfloat16* __restrict__ hi,
    __nv_bfloat16* __restrict__ lo, int n)
{
    int i = blockIdx.x * 256 + threadIdx.x;
    if (i < n) {
        float v = in[i];
        __nv_bfloat16 h = __float2bfloat16(v);
        hi[i] = h;
        lo[i] = __float2bfloat16(v - __bfloat162float(h));
    }
}

// Wqkv [H, D, 3DH] -> transposed [j=h*192+e, d] split
__global__ __launch_bounds__(256) void split_wqkv_kernel(
    const float* __restrict__ W, __nv_bfloat16* __restrict__ hi,
    __nv_bfloat16* __restrict__ lo)
{
    int idx = blockIdx.x * 256 + threadIdx.x;
    if (idx >= J3_ * D_) return;
    int j = idx >> 10, d = idx & 1023;
    int h = j / E3_, e = j % E3_;
    float v = W[((size_t)h * D_ + d) * E3_ + e];
    __nv_bfloat16 vh = __float2bfloat16(v);
    hi[idx] = vh;
    lo[idx] = __float2bfloat16(v - __bfloat162float(vh));
}

// ---------------------------------------------------------------------------
// HMMA GEMM: C[m, n] = sum_k (Ah+Al)[m,k] * (Bh+Bl)[n,k]  (K = 1024)
// C += Ah*Bh + Ah*Bl + Al*Bh  (Al*Bl ~ 2^-18 relative; dropped)
// CTA tile 128x128, 8 warps (2x4), warp tile 64x32, K-chunk 64.
// MODE 0: qkv epilogue (scatter to k/q/v [B,H,N,DH], +bias[j])
// MODE 1: proj epilogue (out[m,j] + bias[j])
// ---------------------------------------------------------------------------
#define LDS_  72                   // smem row stride in bf16 (144 B: LDM conflict-free)
#define TILE_ELEMS (128 * LDS_)    // 9216 bf16 per buffer
#define SA_H 0
#define SA_L (1 * TILE_ELEMS)
#define SB_H (2 * TILE_ELEMS)
#define SB_L (3 * TILE_ELEMS)
#define GEMM_SMEM_BYTES (4 * TILE_ELEMS * 2)   // 73,728 B

template<int MODE>
__global__ __launch_bounds__(256) void gemm_mma(
    const __nv_bfloat16* __restrict__ Ahi, const __nv_bfloat16* __restrict__ Alo,
    const __nv_bfloat16* __restrict__ Bhi, const __nv_bfloat16* __restrict__ Blo,
    const float* __restrict__ bias,
    float* __restrict__ o0, float* __restrict__ o1, float* __restrict__ o2)
{
    extern __shared__ __nv_bfloat16 smem[];
    const int tid  = threadIdx.x;
    const int lane = tid & 31;
    const int wid  = tid >> 5;
    const int wm   = wid >> 2;          // 0..1 -> m offset 0/64
    const int wn   = wid & 3;           // 0..3 -> n offset 0/32/64/96
    const int m0 = blockIdx.x * 128;
    const int n0 = blockIdx.y * 128;

    const uint32_t s_ah = smem_u32(smem) + SA_H * 2;
    const uint32_t s_al = smem_u32(smem) + SA_L * 2;
    const uint32_t s_bh = smem_u32(smem) + SB_H * 2;
    const uint32_t s_bl = smem_u32(smem) + SB_L * 2;

    float acc[4][4][4] = {};   // [m-tile][n-tile][reg]

    // ldmatrix per-lane address components (fixed across k-chunks)
    const uint32_t a_row  = (uint32_t)(wm * 64 + (lane & 15));
    const uint32_t a_coff = (uint32_t)(((lane >> 4) << 3) * 2);       // +8 cols for hi lanes
    const uint32_t b_row  = (uint32_t)(wn * 32 + (lane & 7) + ((lane & 16) >> 1));
    const uint32_t b_coff = (uint32_t)((lane & 8) * 2);               // +8 cols for lanes 8-15/24-31

    for (int kc = 0; kc < 16; kc++) {
        // ---- global -> smem: 4 tiles of 128x64 bf16 ----
        #pragma unroll
        for (int i = 0; i < 4; i++) {
            int u  = tid + i * 256;          // 0..1023 (8-elem units)
            int r  = u >> 3, c8 = u & 7;
            int so = r * LDS_ + c8 * 8;
            size_t ga = (size_t)(m0 + r) * D_ + kc * 64 + c8 * 8;
            size_t gb = (size_t)(n0 + r) * D_ + kc * 64 + c8 * 8;
            *(uint4*)(smem + SA_H + so) = *(const uint4*)(Ahi + ga);
            *(uint4*)(smem + SA_L + so) = *(const uint4*)(Alo + ga);
            *(uint4*)(smem + SB_H + so) = *(const uint4*)(Bhi + gb);
            *(uint4*)(smem + SB_L + so) = *(const uint4*)(Blo + gb);
        }
        __syncthreads();

        // ---- compute: 4 k16 steps ----
        #pragma unroll
        for (int kk = 0; kk < 4; kk++) {
            const uint32_t kb = (uint32_t)(kk * 16 * 2);   // byte offset of k16 step

            uint32_t bhf[2][4], blf[2][4];
            #pragma unroll
            for (int g = 0; g < 2; g++) {
                uint32_t ba = (b_row + g * 16) * (LDS_ * 2) + kb + b_coff;
                LDM4(bhf[g], s_bh + ba);
                LDM4(blf[g], s_bl + ba);
            }

            #pragma unroll
            for (int mt = 0; mt < 4; mt++) {
                uint32_t aa = (a_row + mt * 16) * (LDS_ * 2) + kb + a_coff;
                uint32_t ahf[4], alf[4];
                LDM4(ahf, s_ah + aa);
                LDM4(alf, s_al + aa);
                #pragma unroll
                for (int g = 0; g < 2; g++) {
                    #pragma unroll
                    for (int hf = 0; hf < 2; hf++) {
                        int nt = g * 2 + hf;
                        MMA_BF16(acc[mt][nt], ahf, bhf[g][hf*2], bhf[g][hf*2+1]);
                        MMA_BF16(acc[mt][nt], ahf, blf[g][hf*2], blf[g][hf*2+1]);
                        MMA_BF16(acc[mt][nt], alf, bhf[g][hf*2], bhf[g][hf*2+1]);
                    }
                }
            }
        }
        __syncthreads();
    }

    // ---- epilogue ----
    const int row0 = wm * 64 + (lane >> 2);
    const int col0 = wn * 32 + (lane & 3) * 2;
    #pragma unroll
    for (int mt = 0; mt < 4; mt++) {
        #pragma unroll
        for (int nt = 0; nt < 4; nt++) {
            #pragma unroll
            for (int r = 0; r < 4; r++) {
                int m = m0 + row0 + mt * 16 + (r >> 1) * 8;
                int j = n0 + col0 + nt * 8 + (r & 1);
                float val = acc[mt][nt][r] + bias[j];
                if (MODE == 1) {
                    o0[(size_t)m * D_ + j] = val;
                } else {
                    int b = m >> 11, n = m & (N_ - 1);
                    int h = j / E3_, e = j % E3_;
                    size_t base = ((size_t)(b * H_ + h) * N_ + n) * DH_;
                    if (e < DH_)            o0[base + e] = val;           // k
                    else if (e < 2 * DH_)   o1[base + e - DH_] = val;     // q
                    else                    o2[base + e - 2 * DH_] = val; // v
                }
            }
        }
    }
}

// ---------------------------------------------------------------------------
// Kernel 2: scores[b,h,q,k] = (q . k) / 8 for k-tiles <= q-tile (causal).
// ---------------------------------------------------------------------------
__global__ __launch_bounds__(256) void scores_kernel(
    const float* __restrict__ q, const float* __restrict__ k,
    float* __restrict__ attn)
{
    const int qt = blockIdx.x, kt = blockIdx.y, bh = blockIdx.z;
    if (kt > qt) return;

    __shared__ float qs[64][65];
    __shared__ float ks[64][65];

    const int tid = threadIdx.x;
    const float* qb = q + ((size_t)bh * N_ + qt * 64) * DH_;
    const float* kb = k + ((size_t)bh * N_ + kt * 64) * DH_;

    #pragma unroll
    for (int i = 0; i < 16; i++) {
        int idx = tid + i * 256;
        int r = idx >> 6, c = idx & 63;
        qs[r][c] = qb[(size_t)r * DH_ + c];
        ks[r][c] = kb[(size_t)r * DH_ + c];
    }
    __syncthreads();

    const int ty = tid >> 4, tx = tid & 15;
    float acc[4][4] = {};
    #pragma unroll 8
    for (int d = 0; d < DH_; d++) {
        float a[4], b[4];
        #pragma unroll
        for (int i = 0; i < 4; i++) a[i] = qs[ty * 4 + i][d];
        #pragma unroll
        for (int j = 0; j < 4; j++) b[j] = ks[tx * 4 + j][d];
        #pragma unroll
        for (int i = 0; i < 4; i++)
            #pragma unroll
            for (int j = 0; j < 4; j++)
                acc[i][j] += a[i] * b[j];
    }

    float* abase = attn + (size_t)bh * N_ * N_;
    #pragma unroll
    for (int i = 0; i < 4; i++) {
        int qi = qt * 64 + ty * 4 + i;
        #pragma unroll
        for (int j = 0; j < 4; j++) {
            int ki = kt * 64 + tx * 4 + j;
            abase[(size_t)qi * N_ + ki] = acc[i][j] * 0.125f;
        }
    }
}

// ---------------------------------------------------------------------------
// Kernel 3: row softmax (in place).
// ---------------------------------------------------------------------------
__global__ __launch_bounds__(256) void softmax_kernel(float* __restrict__ attn)
{
    const size_t row = blockIdx.x;
    const int qpos = blockIdx.x & (N_ - 1);
    float* s = attn + row * N_;
    const int tid = threadIdx.x;
    __shared__ float red[256];

    float m = -1e30f;
    for (int i = tid; i <= qpos; i += 256) m = fmaxf(m, s[i]);
    red[tid] = m; __syncthreads();
    #pragma unroll
    for (int o = 128; o > 0; o >>= 1) {
        if (tid < o) red[tid] = fmaxf(red[tid], red[tid + o]);
        __syncthreads();
    }
    m = red[0]; __syncthreads();

    float sum = 0.f;
    for (int i = tid; i <= qpos; i += 256) sum += __expf(s[i] - m);
    red[tid] = sum; __syncthreads();
    #pragma unroll
    for (int o = 128; o > 0; o >>= 1) {
        if (tid < o) red[tid] += red[tid + o];
        __syncthreads();
    }
    const float inv = 1.0f / red[0];

    for (int i = tid; i < N_; i += 256)
        s[i] = (i <= qpos) ? __expf(s[i] - m) * inv : 0.f;
}

// ---------------------------------------------------------------------------
// Kernel 4: sa = attn @ v per (b,h). Output [B, N, H*DH].
// ---------------------------------------------------------------------------
__global__ __launch_bounds__(256) void sa_kernel(
    const float* __restrict__ attn, const float* __restrict__ v,
    float* __restrict__ sa)
{
    const int qt = blockIdx.x, bh = blockIdx.y;
    __shared__ float as[64][65];
    __shared__ float vs[64][65];

    const int tid = threadIdx.x;
    const int ty = tid >> 4, tx = tid & 15;
    float acc[4][4] = {};

    const float* abase = attn + ((size_t)bh * N_ + qt * 64) * N_;
    const float* vbase = v + (size_t)bh * N_ * DH_;

    for (int kt = 0; kt <= qt; kt++) {
        #pragma unroll
        for (int i = 0; i < 16; i++) {
            int idx = tid + i * 256;
            int r = idx >> 6, c = idx & 63;
            as[r][c] = abase[(size_t)r * N_ + kt * 64 + c];
            vs[r][c] = vbase[(size_t)(kt * 64 + r) * DH_ + c];
        }
        __syncthreads();
        #pragma unroll 8
        for (int d = 0; d < 64; d++) {
            float a[4], b[4];
            #pragma unroll
            for (int i = 0; i < 4; i++) a[i] = as[ty * 4 + i][d];
            #pragma unroll
            for (int j = 0; j < 4; j++) b[j] = vs[d][tx * 4 + j];
            #pragma unroll
            for (int i = 0; i < 4; i++)
                #pragma unroll
                for (int j = 0; j < 4; j++)
                    acc[i][j] += a[i] * b[j];
        }
        __syncthreads();
    }

    const int b = bh >> 4, h = bh & 15;
    #pragma unroll
    for (int i = 0; i < 4; i++) {
        int n = qt * 64 + ty * 4 + i;
        #pragma unroll
        for (int j = 0; j < 4; j++)
            sa[((size_t)b * N_ + n) * D_ + h * DH_ + tx * 4 + j] = acc[i][j];
    }
}

// ---------------------------------------------------------------------------
extern "C" void kernel_launch(void* const* d_in, const int* in_sizes, int n_in,
                              void* d_out, int out_size)
{
    const float* x     = (const float*)d_in[0];
    const float* Wqkv  = (const float*)d_in[1];
    const float* bqkv  = (const float*)d_in[2];
    const float* Wproj = (const float*)d_in[3];
    const float* bproj = (const float*)d_in[4];
    float* out = (float*)d_out;

    const size_t OUT_ELEMS  = (size_t)B_ * N_ * D_;
    const size_t ATTN_ELEMS = (size_t)B_ * H_ * N_ * N_;

    float *qp, *kp, *vp, *sap, *attnp;
    cudaGetSymbolAddress((void**)&qp,  g_q);
    cudaGetSymbolAddress((void**)&kp,  g_k);
    cudaGetSymbolAddress((void**)&vp,  g_v);
    cudaGetSymbolAddress((void**)&sap, g_sa);
    cudaGetSymbolAddress((void**)&attnp, g_attn);

    __nv_bfloat16 *xhi, *xlo, *wqhi, *wqlo, *wphi, *wplo, *sahi, *salo;
    cudaGetSymbolAddress((void**)&xhi,  g_xhi);
    cudaGetSymbolAddress((void**)&xlo,  g_xlo);
    cudaGetSymbolAddress((void**)&wqhi, g_wqhi);
    cudaGetSymbolAddress((void**)&wqlo, g_wqlo);
    cudaGetSymbolAddress((void**)&wphi, g_wphi);
    cudaGetSymbolAddress((void**)&wplo, g_wplo);
    cudaGetSymbolAddress((void**)&sahi, g_sahi);
    cudaGetSymbolAddress((void**)&salo, g_salo);

    if ((size_t)out_size >= OUT_ELEMS + ATTN_ELEMS)
        attnp = out + OUT_ELEMS;   // tuple output (out, attn) flattened

    cudaFuncSetAttribute(gemm_mma<0>, cudaFuncAttributeMaxDynamicSharedMemorySize, GEMM_SMEM_BYTES);
    cudaFuncSetAttribute(gemm_mma<1>, cudaFuncAttributeMaxDynamicSharedMemorySize, GEMM_SMEM_BYTES);

    // 0) bf16 splits of inputs
    split_kernel<<<(M_ * D_ + 255) / 256, 256>>>(x, xhi, xlo, M_ * D_);
    split_wqkv_kernel<<<(J3_ * D_ + 255) / 256, 256>>>(Wqkv, wqhi, wqlo);
    split_kernel<<<(D_ * D_ + 255) / 256, 256>>>(Wproj, wphi, wplo, D_ * D_);

    // 1) QKV projection on tensor cores (HMMA)
    gemm_mma<0><<<dim3(M_ / 128, J3_ / 128), 256, GEMM_SMEM_BYTES>>>(
        xhi, xlo, wqhi, wqlo, bqkv, kp, qp, vp);

    // 2) causal scores
    scores_kernel<<<dim3(N_ / 64, N_ / 64, B_ * H_), 256>>>(qp, kp, attnp);
    // 3) row softmax (in place)
    softmax_kernel<<<B_ * H_ * N_, 256>>>(attnp);
    // 4) sa = attn @ v
    sa_kernel<<<dim3(N_ / 64, B_ * H_), 256>>>(attnp, vp, sap);

    // 5) output projection on tensor cores (HMMA)
    split_kernel<<<(M_ * D_ + 255) / 256, 256>>>(sap, sahi, salo, M_ * D_);
    gemm_mma<1><<<dim3(M_ / 128, D_ / 128), 256, GEMM_SMEM_BYTES>>>(
        sahi, salo, wphi, wplo, bproj, out, nullptr, nullptr);
}

// round 4
// speedup vs baseline: 2.4376x; 1.4472x over previous
#include <cuda_runtime.h>
#include <cuda_bf16.h>
#include <math.h>
#include <stdint.h>

// Problem constants
#define B_  2
#define N_  2048
#define D_  1024
#define H_  16
#define DH_ 64
#define E3_ 192           // 3*DH per head, chunk order (k,q,v)
#define J3_ 3072          // H * 3*DH
#define M_  4096          // B*N

// ---------------------------------------------------------------------------
// Scratch (device globals)
// ---------------------------------------------------------------------------
__device__ float g_attn[(size_t)B_*H_*N_*N_];        // fallback if attn not in d_out

__device__ __nv_bfloat16 g_xhi [(size_t)M_*D_];
__device__ __nv_bfloat16 g_xlo [(size_t)M_*D_];
__device__ __nv_bfloat16 g_wqhi[(size_t)J3_*D_];     // Wqkv transposed [j, d]
__device__ __nv_bfloat16 g_wqlo[(size_t)J3_*D_];
__device__ __nv_bfloat16 g_wphi[(size_t)D_*D_];
__device__ __nv_bfloat16 g_wplo[(size_t)D_*D_];
__device__ __nv_bfloat16 g_sahi[(size_t)M_*D_];
__device__ __nv_bfloat16 g_salo[(size_t)M_*D_];

// q/k [B,H,N,DH]; v transposed [B,H,DH,N]; all bf16 hi/lo
__device__ __nv_bfloat16 g_qh[(size_t)B_*H_*N_*DH_];
__device__ __nv_bfloat16 g_ql[(size_t)B_*H_*N_*DH_];
__device__ __nv_bfloat16 g_kh[(size_t)B_*H_*N_*DH_];
__device__ __nv_bfloat16 g_kl[(size_t)B_*H_*N_*DH_];
__device__ __nv_bfloat16 g_vth[(size_t)B_*H_*DH_*N_];
__device__ __nv_bfloat16 g_vtl[(size_t)B_*H_*DH_*N_];

// attn probabilities, bf16 hi/lo [B,H,N,N]
__device__ __nv_bfloat16 g_pbh[(size_t)B_*H_*N_*N_];
__device__ __nv_bfloat16 g_pbl[(size_t)B_*H_*N_*N_];

// ---------------------------------------------------------------------------
// mma.sync / ldmatrix helpers (base sm_103 features)
// ---------------------------------------------------------------------------
__device__ __forceinline__ uint32_t smem_u32(const void* p) {
    uint32_t a;
    asm("{ .reg .u64 t; cvta.to.shared.u64 t, %1; cvt.u32.u64 %0, t; }"
        : "=r"(a) : "l"(p));
    return a;
}

#define LDM4(r, addr)                                                         \
    asm volatile("ldmatrix.sync.aligned.m8n8.x4.shared.b16 {%0,%1,%2,%3}, [%4];" \
        : "=r"((r)[0]), "=r"((r)[1]), "=r"((r)[2]), "=r"((r)[3])              \
        : "r"(addr))

#define MMA_BF16(c, a, b0, b1)                                                \
    asm volatile("mma.sync.aligned.m16n8k16.row.col.f32.bf16.bf16.f32 "       \
        "{%0,%1,%2,%3}, {%4,%5,%6,%7}, {%8,%9}, {%0,%1,%2,%3};"               \
        : "+f"((c)[0]), "+f"((c)[1]), "+f"((c)[2]), "+f"((c)[3])              \
        : "r"((a)[0]), "r"((a)[1]), "r"((a)[2]), "r"((a)[3]), "r"(b0), "r"(b1))

__device__ __forceinline__ void bf_split(float v, __nv_bfloat16& h, __nv_bfloat16& l) {
    h = __float2bfloat16(v);
    l = __float2bfloat16(v - __bfloat162float(h));
}

// ---------------------------------------------------------------------------
// bf16 hi/lo split conversion kernels
// ---------------------------------------------------------------------------
__global__ __launch_bounds__(256) void split_kernel(
    const float* __restrict__ in, __nv_bfloat16* __restrict__ hi,
    __nv_bfloat16* __restrict__ lo, int n)
{
    int i = blockIdx.x * 256 + threadIdx.x;
    if (i < n) {
        float v = in[i];
        __nv_bfloat16 h, l; bf_split(v, h, l);
        hi[i] = h; lo[i] = l;
    }
}

__global__ __launch_bounds__(256) void split_wqkv_kernel(
    const float* __restrict__ W, __nv_bfloat16* __restrict__ hi,
    __nv_bfloat16* __restrict__ lo)
{
    int idx = blockIdx.x * 256 + threadIdx.x;
    if (idx >= J3_ * D_) return;
    int j = idx >> 10, d = idx & 1023;
    int h = j / E3_, e = j % E3_;
    float v = W[((size_t)h * D_ + d) * E3_ + e];
    __nv_bfloat16 vh, vl; bf_split(v, vh, vl);
    hi[idx] = vh; lo[idx] = vl;
}

// ---------------------------------------------------------------------------
// HMMA GEMM (validated R3): C = (Ah+Al)(Bh+Bl)^T, 3-term split, K = 1024.
// CTA 128x128, 8 warps (2x4), warp tile 64x32, K-chunk 64.
// MODE 0: qkv epilogue -> bf16 hi/lo k,q (std layout) + v (transposed)
// MODE 1: proj epilogue -> fp32 out + bias
// ---------------------------------------------------------------------------
#define LDS_  72
#define TILE_ELEMS (128 * LDS_)
#define SA_H 0
#define SA_L (1 * TILE_ELEMS)
#define SB_H (2 * TILE_ELEMS)
#define SB_L (3 * TILE_ELEMS)
#define GEMM_SMEM_BYTES (4 * TILE_ELEMS * 2)   // 73,728 B

template<int MODE>
__global__ __launch_bounds__(256) void gemm_mma(
    const __nv_bfloat16* __restrict__ Ahi, const __nv_bfloat16* __restrict__ Alo,
    const __nv_bfloat16* __restrict__ Bhi, const __nv_bfloat16* __restrict__ Blo,
    const float* __restrict__ bias,
    float* __restrict__ oF,
    __nv_bfloat16* __restrict__ okh, __nv_bfloat16* __restrict__ okl,
    __nv_bfloat16* __restrict__ oqh, __nv_bfloat16* __restrict__ oql,
    __nv_bfloat16* __restrict__ ovh, __nv_bfloat16* __restrict__ ovl)
{
    extern __shared__ __nv_bfloat16 smem[];
    const int tid  = threadIdx.x;
    const int lane = tid & 31;
    const int wid  = tid >> 5;
    const int wm   = wid >> 2;
    const int wn   = wid & 3;
    const int m0 = blockIdx.x * 128;
    const int n0 = blockIdx.y * 128;

    const uint32_t s_ah = smem_u32(smem) + SA_H * 2;
    const uint32_t s_al = smem_u32(smem) + SA_L * 2;
    const uint32_t s_bh = smem_u32(smem) + SB_H * 2;
    const uint32_t s_bl = smem_u32(smem) + SB_L * 2;

    float acc[4][4][4] = {};

    const uint32_t a_row  = (uint32_t)(wm * 64 + (lane & 15));
    const uint32_t a_coff = (uint32_t)(((lane >> 4) << 3) * 2);
    const uint32_t b_row  = (uint32_t)(wn * 32 + (lane & 7) + ((lane & 16) >> 1));
    const uint32_t b_coff = (uint32_t)((lane & 8) * 2);

    for (int kc = 0; kc < 16; kc++) {
        #pragma unroll
        for (int i = 0; i < 4; i++) {
            int u  = tid + i * 256;
            int r  = u >> 3, c8 = u & 7;
            int so = r * LDS_ + c8 * 8;
            size_t ga = (size_t)(m0 + r) * D_ + kc * 64 + c8 * 8;
            size_t gb = (size_t)(n0 + r) * D_ + kc * 64 + c8 * 8;
            *(uint4*)(smem + SA_H + so) = *(const uint4*)(Ahi + ga);
            *(uint4*)(smem + SA_L + so) = *(const uint4*)(Alo + ga);
            *(uint4*)(smem + SB_H + so) = *(const uint4*)(Bhi + gb);
            *(uint4*)(smem + SB_L + so) = *(const uint4*)(Blo + gb);
        }
        __syncthreads();

        #pragma unroll
        for (int kk = 0; kk < 4; kk++) {
            const uint32_t kb = (uint32_t)(kk * 16 * 2);
            uint32_t bhf[2][4], blf[2][4];
            #pragma unroll
            for (int g = 0; g < 2; g++) {
                uint32_t ba = (b_row + g * 16) * (LDS_ * 2) + kb + b_coff;
                LDM4(bhf[g], s_bh + ba);
                LDM4(blf[g], s_bl + ba);
            }
            #pragma unroll
            for (int mt = 0; mt < 4; mt++) {
                uint32_t aa = (a_row + mt * 16) * (LDS_ * 2) + kb + a_coff;
                uint32_t ahf[4], alf[4];
                LDM4(ahf, s_ah + aa);
                LDM4(alf, s_al + aa);
                #pragma unroll
                for (int g = 0; g < 2; g++) {
                    #pragma unroll
                    for (int hf = 0; hf < 2; hf++) {
                        int nt = g * 2 + hf;
                        MMA_BF16(acc[mt][nt], ahf, bhf[g][hf*2], bhf[g][hf*2+1]);
                        MMA_BF16(acc[mt][nt], ahf, blf[g][hf*2], blf[g][hf*2+1]);
                        MMA_BF16(acc[mt][nt], alf, bhf[g][hf*2], bhf[g][hf*2+1]);
                    }
                }
            }
        }
        __syncthreads();
    }

    const int row0 = wm * 64 + (lane >> 2);
    const int col0 = wn * 32 + (lane & 3) * 2;
    #pragma unroll
    for (int mt = 0; mt < 4; mt++) {
        #pragma unroll
        for (int nt = 0; nt < 4; nt++) {
            #pragma unroll
            for (int r = 0; r < 4; r++) {
                int m = m0 + row0 + mt * 16 + (r >> 1) * 8;
                int j = n0 + col0 + nt * 8 + (r & 1);
                float val = acc[mt][nt][r] + bias[j];
                if (MODE == 1) {
                    oF[(size_t)m * D_ + j] = val;
                } else {
                    int b = m >> 11, n = m & (N_ - 1);
                    int h = j / E3_, e = j % E3_;
                    __nv_bfloat16 vh, vl; bf_split(val, vh, vl);
                    if (e < DH_) {
                        size_t o = ((size_t)(b * H_ + h) * N_ + n) * DH_ + e;
                        okh[o] = vh; okl[o] = vl;
                    } else if (e < 2 * DH_) {
                        size_t o = ((size_t)(b * H_ + h) * N_ + n) * DH_ + (e - DH_);
                        oqh[o] = vh; oql[o] = vl;
                    } else {
                        size_t o = ((size_t)(b * H_ + h) * DH_ + (e - 2 * DH_)) * N_ + n;
                        ovh[o] = vh; ovl[o] = vl;
                    }
                }
            }
        }
    }
}

// ---------------------------------------------------------------------------
// scores_mma: scores[bh, q, k] = (q . k) / 8, 128x128 tiles, kt <= qt, K=64.
// ---------------------------------------------------------------------------
__global__ __launch_bounds__(256) void scores_mma(
    const __nv_bfloat16* __restrict__ Qh, const __nv_bfloat16* __restrict__ Ql,
    const __nv_bfloat16* __restrict__ Kh, const __nv_bfloat16* __restrict__ Kl,
    float* __restrict__ attn)
{
    const int qt = blockIdx.x, kt = blockIdx.y, bh = blockIdx.z;
    if (kt > qt) return;

    extern __shared__ __nv_bfloat16 smem[];
    const int tid  = threadIdx.x;
    const int lane = tid & 31;
    const int wid  = tid >> 5;
    const int wm   = wid >> 2;
    const int wn   = wid & 3;

    const uint32_t s_ah = smem_u32(smem) + SA_H * 2;
    const uint32_t s_al = smem_u32(smem) + SA_L * 2;
    const uint32_t s_bh = smem_u32(smem) + SB_H * 2;
    const uint32_t s_bl = smem_u32(smem) + SB_L * 2;

    const __nv_bfloat16* qhb = Qh + ((size_t)bh * N_ + qt * 128) * DH_;
    const __nv_bfloat16* qlb = Ql + ((size_t)bh * N_ + qt * 128) * DH_;
    const __nv_bfloat16* khb = Kh + ((size_t)bh * N_ + kt * 128) * DH_;
    const __nv_bfloat16* klb = Kl + ((size_t)bh * N_ + kt * 128) * DH_;

    // load 4 tiles of 128x64 bf16
    #pragma unroll
    for (int i = 0; i < 4; i++) {
        int u  = tid + i * 256;
        int r  = u >> 3, c8 = u & 7;
        int so = r * LDS_ + c8 * 8;
        size_t g = (size_t)r * DH_ + c8 * 8;
        *(uint4*)(smem + SA_H + so) = *(const uint4*)(qhb + g);
        *(uint4*)(smem + SA_L + so) = *(const uint4*)(qlb + g);
        *(uint4*)(smem + SB_H + so) = *(const uint4*)(khb + g);
        *(uint4*)(smem + SB_L + so) = *(const uint4*)(klb + g);
    }
    __syncthreads();

    const uint32_t a_row  = (uint32_t)(wm * 64 + (lane & 15));
    const uint32_t a_coff = (uint32_t)(((lane >> 4) << 3) * 2);
    const uint32_t b_row  = (uint32_t)(wn * 32 + (lane & 7) + ((lane & 16) >> 1));
    const uint32_t b_coff = (uint32_t)((lane & 8) * 2);

    float acc[4][4][4] = {};
    #pragma unroll
    for (int kk = 0; kk < 4; kk++) {
        const uint32_t kb = (uint32_t)(kk * 16 * 2);
        uint32_t bhf[2][4], blf[2][4];
        #pragma unroll
        for (int g = 0; g < 2; g++) {
            uint32_t ba = (b_row + g * 16) * (LDS_ * 2) + kb + b_coff;
            LDM4(bhf[g], s_bh + ba);
            LDM4(blf[g], s_bl + ba);
        }
        #pragma unroll
        for (int mt = 0; mt < 4; mt++) {
            uint32_t aa = (a_row + mt * 16) * (LDS_ * 2) + kb + a_coff;
            uint32_t ahf[4], alf[4];
            LDM4(ahf, s_ah + aa);
            LDM4(alf, s_al + aa);
            #pragma unroll
            for (int g = 0; g < 2; g++) {
                #pragma unroll
                for (int hf = 0; hf < 2; hf++) {
                    int nt = g * 2 + hf;
                    MMA_BF16(acc[mt][nt], ahf, bhf[g][hf*2], bhf[g][hf*2+1]);
                    MMA_BF16(acc[mt][nt], ahf, blf[g][hf*2], blf[g][hf*2+1]);
                    MMA_BF16(acc[mt][nt], alf, bhf[g][hf*2], bhf[g][hf*2+1]);
                }
            }
        }
    }

    float* abase = attn + (size_t)bh * N_ * N_;
    const int row0 = wm * 64 + (lane >> 2);
    const int col0 = wn * 32 + (lane & 3) * 2;
    #pragma unroll
    for (int mt = 0; mt < 4; mt++) {
        #pragma unroll
        for (int nt = 0; nt < 4; nt++) {
            #pragma unroll
            for (int r = 0; r < 4; r++) {
                int qi = qt * 128 + row0 + mt * 16 + (r >> 1) * 8;
                int ki = kt * 128 + col0 + nt * 8 + (r & 1);
                abase[(size_t)qi * N_ + ki] = acc[mt][nt][r] * 0.125f;
            }
        }
    }
}

// ---------------------------------------------------------------------------
// softmax2: row softmax, smem-cached. Writes fp32 attn (full row, zeros above
// diagonal) + bf16 hi/lo probs up to the 128-aligned causal boundary.
// ---------------------------------------------------------------------------
__global__ __launch_bounds__(256) void softmax2(
    float* __restrict__ attn,
    __nv_bfloat16* __restrict__ pbh, __nv_bfloat16* __restrict__ pbl)
{
    __shared__ float row[N_];
    __shared__ float red[256];

    const size_t r = blockIdx.x;
    const int qpos = blockIdx.x & (N_ - 1);
    const int kmax = ((qpos >> 7) + 1) << 7;
    float* s = attn + r * N_;
    __nv_bfloat16* ph = pbh + r * N_;
    __nv_bfloat16* pl = pbl + r * N_;
    const int tid = threadIdx.x;

    float m = -1e30f;
    for (int i = tid; i <= qpos; i += 256) {
        float v = s[i];
        row[i] = v;
        m = fmaxf(m, v);
    }
    red[tid] = m; __syncthreads();
    #pragma unroll
    for (int o = 128; o > 0; o >>= 1) {
        if (tid < o) red[tid] = fmaxf(red[tid], red[tid + o]);
        __syncthreads();
    }
    m = red[0]; __syncthreads();

    float sum = 0.f;
    for (int i = tid; i <= qpos; i += 256) {
        float e = __expf(row[i] - m);
        row[i] = e;
        sum += e;
    }
    red[tid] = sum; __syncthreads();
    #pragma unroll
    for (int o = 128; o > 0; o >>= 1) {
        if (tid < o) red[tid] += red[tid + o];
        __syncthreads();
    }
    const float inv = 1.0f / red[0];

    for (int i = tid; i < N_; i += 256) {
        float p = (i <= qpos) ? row[i] * inv : 0.f;
        s[i] = p;
        if (i < kmax) {
            __nv_bfloat16 h, l; bf_split(p, h, l);
            ph[i] = h; pl[i] = l;
        }
    }
}

// ---------------------------------------------------------------------------
// sa_mma: sa[q, dh] = sum_k p[q,k] * v[k,dh] per (qt, bh). Output bf16 hi/lo
// into sahi/salo [B, N, H*DH]. 8 warps (2x4), warp tile 64x16, K-chunk 128.
// ---------------------------------------------------------------------------
#define LDS2_ 136
#define SP_H 0
#define SP_L (128 * LDS2_)
#define SV_H (2 * 128 * LDS2_)
#define SV_L (2 * 128 * LDS2_ + 64 * LDS2_)
#define SA2_SMEM_BYTES ((2 * 128 * LDS2_ + 2 * 64 * LDS2_) * 2)   // 104,448 B

__global__ __launch_bounds__(256) void sa_mma(
    const __nv_bfloat16* __restrict__ Ph, const __nv_bfloat16* __restrict__ Pl,
    const __nv_bfloat16* __restrict__ Vth, const __nv_bfloat16* __restrict__ Vtl,
    __nv_bfloat16* __restrict__ sahi, __nv_bfloat16* __restrict__ salo)
{
    extern __shared__ __nv_bfloat16 smem[];
    const int qt = blockIdx.x, bh = blockIdx.y;
    const int tid  = threadIdx.x;
    const int lane = tid & 31;
    const int wid  = tid >> 5;
    const int wm   = wid >> 2;          // 0..1 -> rows 0/64
    const int wn   = wid & 3;           // 0..3 -> cols 0/16/32/48

    const uint32_t s_ph = smem_u32(smem) + SP_H * 2;
    const uint32_t s_pl = smem_u32(smem) + SP_L * 2;
    const uint32_t s_vh = smem_u32(smem) + SV_H * 2;
    const uint32_t s_vl = smem_u32(smem) + SV_L * 2;

    const __nv_bfloat16* phb = Ph + ((size_t)bh * N_ + qt * 128) * N_;
    const __nv_bfloat16* plb = Pl + ((size_t)bh * N_ + qt * 128) * N_;
    const __nv_bfloat16* vhb = Vth + (size_t)bh * DH_ * N_;
    const __nv_bfloat16* vlb = Vtl + (size_t)bh * DH_ * N_;

    float acc[4][2][4] = {};

    const uint32_t a_row  = (uint32_t)(wm * 64 + (lane & 15));
    const uint32_t a_coff = (uint32_t)(((lane >> 4) << 3) * 2);
    const uint32_t b_row  = (uint32_t)(wn * 16 + (lane & 7) + ((lane & 16) >> 1));
    const uint32_t b_coff = (uint32_t)((lane & 8) * 2);

    for (int kt = 0; kt <= qt; kt++) {
        // p tiles: 128 rows x 128 cols; v tiles: 64 rows x 128 cols
        #pragma unroll
        for (int i = 0; i < 8; i++) {
            int u  = tid + i * 256;           // 0..2047
            int r  = u >> 4, c8 = u & 15;
            int so = r * LDS2_ + c8 * 8;
            size_t g = (size_t)r * N_ + kt * 128 + c8 * 8;
            *(uint4*)(smem + SP_H + so) = *(const uint4*)(phb + g);
            *(uint4*)(smem + SP_L + so) = *(const uint4*)(plb + g);
        }
        #pragma unroll
        for (int i = 0; i < 4; i++) {
            int u  = tid + i * 256;           // 0..1023
            int r  = u >> 4, c8 = u & 15;
            int so = r * LDS2_ + c8 * 8;
            size_t g = (size_t)r * N_ + kt * 128 + c8 * 8;
            *(uint4*)(smem + SV_H + so) = *(const uint4*)(vhb + g);
            *(uint4*)(smem + SV_L + so) = *(const uint4*)(vlb + g);
        }
        __syncthreads();

        #pragma unroll
        for (int kk = 0; kk < 8; kk++) {
            const uint32_t kb = (uint32_t)(kk * 16 * 2);
            uint32_t bhf[4], blf[4];
            uint32_t ba = b_row * (LDS2_ * 2) + kb + b_coff;
            LDM4(bhf, s_vh + ba);
            LDM4(blf, s_vl + ba);
            #pragma unroll
            for (int mt = 0; mt < 4; mt++) {
                uint32_t aa = (a_row + mt * 16) * (LDS2_ * 2) + kb + a_coff;
                uint32_t ahf[4], alf[4];
                LDM4(ahf, s_ph + aa);
                LDM4(alf, s_pl + aa);
                #pragma unroll
                for (int nt = 0; nt < 2; nt++) {
                    MMA_BF16(acc[mt][nt], ahf, bhf[nt*2], bhf[nt*2+1]);
                    MMA_BF16(acc[mt][nt], ahf, blf[nt*2], blf[nt*2+1]);
                    MMA_BF16(acc[mt][nt], alf, bhf[nt*2], bhf[nt*2+1]);
                }
            }
        }
        __syncthreads();
    }

    const int b = bh >> 4, h = bh & 15;
    const int row0 = wm * 64 + (lane >> 2);
    const int col0 = wn * 16 + (lane & 3) * 2;
    #pragma unroll
    for (int mt = 0; mt < 4; mt++) {
        #pragma unroll
        for (int nt = 0; nt < 2; nt++) {
            #pragma unroll
            for (int r = 0; r < 4; r++) {
                int n  = qt * 128 + row0 + mt * 16 + (r >> 1) * 8;
                int dh = col0 + nt * 8 + (r & 1);
                size_t o = ((size_t)b * N_ + n) * D_ + h * DH_ + dh;
                __nv_bfloat16 vh, vl; bf_split(acc[mt][nt][r], vh, vl);
                sahi[o] = vh; salo[o] = vl;
            }
        }
    }
}

// ---------------------------------------------------------------------------
extern "C" void kernel_launch(void* const* d_in, const int* in_sizes, int n_in,
                              void* d_out, int out_size)
{
    const float* x     = (const float*)d_in[0];
    const float* Wqkv  = (const float*)d_in[1];
    const float* bqkv  = (const float*)d_in[2];
    const float* Wproj = (const float*)d_in[3];
    const float* bproj = (const float*)d_in[4];
    float* out = (float*)d_out;

    const size_t OUT_ELEMS  = (size_t)B_ * N_ * D_;
    const size_t ATTN_ELEMS = (size_t)B_ * H_ * N_ * N_;

    float* attnp;
    cudaGetSymbolAddress((void**)&attnp, g_attn);
    if ((size_t)out_size >= OUT_ELEMS + ATTN_ELEMS)
        attnp = out + OUT_ELEMS;   // tuple output (out, attn)

    __nv_bfloat16 *xhi, *xlo, *wqhi, *wqlo, *wphi, *wplo, *sahi, *salo;
    __nv_bfloat16 *qh, *ql, *kh, *kl, *vth, *vtl, *pbh, *pbl;
    cudaGetSymbolAddress((void**)&xhi,  g_xhi);
    cudaGetSymbolAddress((void**)&xlo,  g_xlo);
    cudaGetSymbolAddress((void**)&wqhi, g_wqhi);
    cudaGetSymbolAddress((void**)&wqlo, g_wqlo);
    cudaGetSymbolAddress((void**)&wphi, g_wphi);
    cudaGetSymbolAddress((void**)&wplo, g_wplo);
    cudaGetSymbolAddress((void**)&sahi, g_sahi);
    cudaGetSymbolAddress((void**)&salo, g_salo);
    cudaGetSymbolAddress((void**)&qh,   g_qh);
    cudaGetSymbolAddress((void**)&ql,   g_ql);
    cudaGetSymbolAddress((void**)&kh,   g_kh);
    cudaGetSymbolAddress((void**)&kl,   g_kl);
    cudaGetSymbolAddress((void**)&vth,  g_vth);
    cudaGetSymbolAddress((void**)&vtl,  g_vtl);
    cudaGetSymbolAddress((void**)&pbh,  g_pbh);
    cudaGetSymbolAddress((void**)&pbl,  g_pbl);

    cudaFuncSetAttribute(gemm_mma<0>, cudaFuncAttributeMaxDynamicSharedMemorySize, GEMM_SMEM_BYTES);
    cudaFuncSetAttribute(gemm_mma<1>, cudaFuncAttributeMaxDynamicSharedMemorySize, GEMM_SMEM_BYTES);
    cudaFuncSetAttribute(scores_mma,  cudaFuncAttributeMaxDynamicSharedMemorySize, GEMM_SMEM_BYTES);
    cudaFuncSetAttribute(sa_mma,      cudaFuncAttributeMaxDynamicSharedMemorySize, SA2_SMEM_BYTES);

    // 0) bf16 splits of inputs
    split_kernel<<<(M_ * D_ + 255) / 256, 256>>>(x, xhi, xlo, M_ * D_);
    split_wqkv_kernel<<<(J3_ * D_ + 255) / 256, 256>>>(Wqkv, wqhi, wqlo);
    split_kernel<<<(D_ * D_ + 255) / 256, 256>>>(Wproj, wphi, wplo, D_ * D_);

    // 1) QKV projection -> bf16 hi/lo q,k (std) + v (transposed)
    gemm_mma<0><<<dim3(M_ / 128, J3_ / 128), 256, GEMM_SMEM_BYTES>>>(
        xhi, xlo, wqhi, wqlo, bqkv, nullptr, kh, kl, qh, ql, vth, vtl);

    // 2) causal scores on tensor cores
    scores_mma<<<dim3(N_ / 128, N_ / 128, B_ * H_), 256, GEMM_SMEM_BYTES>>>(
        qh, ql, kh, kl, attnp);

    // 3) row softmax -> fp32 attn + bf16 hi/lo probs
    softmax2<<<B_ * H_ * N_, 256>>>(attnp, pbh, pbl);

    // 4) sa = attn @ v on tensor cores -> bf16 hi/lo sa
    sa_mma<<<dim3(N_ / 128, B_ * H_), 256, SA2_SMEM_BYTES>>>(
        pbh, pbl, vth, vtl, sahi, salo);

    // 5) output projection
    gemm_mma<1><<<dim3(M_ / 128, D_ / 128), 256, GEMM_SMEM_BYTES>>>(
        sahi, salo, wphi, wplo, bproj, out,
        nullptr, nullptr, nullptr, nullptr, nullptr, nullptr);
}

// round 5
// speedup vs baseline: 2.7059x; 1.1101x over previous
#include <cuda_runtime.h>
#include <cuda_bf16.h>
#include <math.h>
#include <stdint.h>

// Problem constants
#define B_  2
#define N_  2048
#define D_  1024
#define H_  16
#define DH_ 64
#define E3_ 192
#define J3_ 3072
#define M_  4096

// ---------------------------------------------------------------------------
// Scratch (device globals)
// ---------------------------------------------------------------------------
__device__ float g_attn[(size_t)B_*H_*N_*N_];

__device__ __nv_bfloat16 g_xhi [(size_t)M_*D_];
__device__ __nv_bfloat16 g_xlo [(size_t)M_*D_];
__device__ __nv_bfloat16 g_wqhi[(size_t)J3_*D_];
__device__ __nv_bfloat16 g_wqlo[(size_t)J3_*D_];
__device__ __nv_bfloat16 g_wphi[(size_t)D_*D_];
__device__ __nv_bfloat16 g_wplo[(size_t)D_*D_];
__device__ __nv_bfloat16 g_sahi[(size_t)M_*D_];
__device__ __nv_bfloat16 g_salo[(size_t)M_*D_];

__device__ __nv_bfloat16 g_qh[(size_t)B_*H_*N_*DH_];
__device__ __nv_bfloat16 g_ql[(size_t)B_*H_*N_*DH_];
__device__ __nv_bfloat16 g_kh[(size_t)B_*H_*N_*DH_];
__device__ __nv_bfloat16 g_kl[(size_t)B_*H_*N_*DH_];
__device__ __nv_bfloat16 g_vth[(size_t)B_*H_*DH_*N_];
__device__ __nv_bfloat16 g_vtl[(size_t)B_*H_*DH_*N_];

__device__ __nv_bfloat16 g_pbh[(size_t)B_*H_*N_*N_];
__device__ __nv_bfloat16 g_pbl[(size_t)B_*H_*N_*N_];

// ---------------------------------------------------------------------------
// Helpers
// ---------------------------------------------------------------------------
__device__ __forceinline__ uint32_t smem_u32(const void* p) {
    uint32_t a;
    asm("{ .reg .u64 t; cvta.to.shared.u64 t, %1; cvt.u32.u64 %0, t; }"
        : "=r"(a) : "l"(p));
    return a;
}

#define LDM4(r, addr)                                                         \
    asm volatile("ldmatrix.sync.aligned.m8n8.x4.shared.b16 {%0,%1,%2,%3}, [%4];" \
        : "=r"((r)[0]), "=r"((r)[1]), "=r"((r)[2]), "=r"((r)[3])              \
        : "r"(addr))

#define MMA_BF16(c, a, b0, b1)                                                \
    asm volatile("mma.sync.aligned.m16n8k16.row.col.f32.bf16.bf16.f32 "       \
        "{%0,%1,%2,%3}, {%4,%5,%6,%7}, {%8,%9}, {%0,%1,%2,%3};"               \
        : "+f"((c)[0]), "+f"((c)[1]), "+f"((c)[2]), "+f"((c)[3])              \
        : "r"((a)[0]), "r"((a)[1]), "r"((a)[2]), "r"((a)[3]), "r"(b0), "r"(b1))

#define CP16(dst, src)                                                        \
    asm volatile("cp.async.cg.shared.global [%0], [%1], 16;"                  \
        :: "r"(dst), "l"(src))
#define CP_COMMIT() asm volatile("cp.async.commit_group;" ::: "memory")
#define CP_WAIT0()  asm volatile("cp.async.wait_group 0;" ::: "memory")
#define CP_WAIT1()  asm volatile("cp.async.wait_group 1;" ::: "memory")

__device__ __forceinline__ void bf_split(float v, __nv_bfloat16& h, __nv_bfloat16& l) {
    h = __float2bfloat16(v);
    l = __float2bfloat16(v - __bfloat162float(h));
}

// ---------------------------------------------------------------------------
// split kernels
// ---------------------------------------------------------------------------
__global__ __launch_bounds__(256) void split_kernel(
    const float* __restrict__ in, __nv_bfloat16* __restrict__ hi,
    __nv_bfloat16* __restrict__ lo, int n)
{
    int i = blockIdx.x * 256 + threadIdx.x;
    if (i < n) {
        float v = in[i];
        __nv_bfloat16 h, l; bf_split(v, h, l);
        hi[i] = h; lo[i] = l;
    }
}

__global__ __launch_bounds__(256) void split_wqkv_kernel(
    const float* __restrict__ W, __nv_bfloat16* __restrict__ hi,
    __nv_bfloat16* __restrict__ lo)
{
    int idx = blockIdx.x * 256 + threadIdx.x;
    if (idx >= J3_ * D_) return;
    int j = idx >> 10, d = idx & 1023;
    int h = j / E3_, e = j % E3_;
    float v = W[((size_t)h * D_ + d) * E3_ + e];
    __nv_bfloat16 vh, vl; bf_split(v, vh, vl);
    hi[idx] = vh; lo[idx] = vl;
}

// ---------------------------------------------------------------------------
// gemm_pipe: 2-stage cp.async pipelined split-bf16 GEMM, K=1024, chunk 32.
// CTA 128x128, 8 warps (2x4), warp tile 64x32.
// MODE 0: qkv epilogue; MODE 1: proj epilogue.
// Stage layout (bytes): AH=0, AL=10240, BH=20480, BL=30720; stage=40960.
// ---------------------------------------------------------------------------
#define GP_LDS 40
#define GP_AH 0
#define GP_AL 10240
#define GP_BH 20480
#define GP_BL 30720
#define GP_STAGE 40960
#define GP_SMEM (2 * GP_STAGE)          // 81,920 B

template<int MODE>
__global__ __launch_bounds__(256) void gemm_pipe(
    const __nv_bfloat16* __restrict__ Ahi, const __nv_bfloat16* __restrict__ Alo,
    const __nv_bfloat16* __restrict__ Bhi, const __nv_bfloat16* __restrict__ Blo,
    const float* __restrict__ bias,
    float* __restrict__ oF,
    __nv_bfloat16* __restrict__ okh, __nv_bfloat16* __restrict__ okl,
    __nv_bfloat16* __restrict__ oqh, __nv_bfloat16* __restrict__ oql,
    __nv_bfloat16* __restrict__ ovh, __nv_bfloat16* __restrict__ ovl)
{
    extern __shared__ __nv_bfloat16 smem[];
    const uint32_t sb0 = smem_u32(smem);
    const int tid  = threadIdx.x;
    const int lane = tid & 31;
    const int wid  = tid >> 5;
    const int wm   = wid >> 2;
    const int wn   = wid & 3;
    const int m0 = blockIdx.x * 128;
    const int n0 = blockIdx.y * 128;

    float acc[4][4][4] = {};

    const uint32_t a_row  = (uint32_t)(wm * 64 + (lane & 15));
    const uint32_t a_coff = (uint32_t)(((lane >> 4) << 3) * 2);
    const uint32_t b_row  = (uint32_t)(wn * 32 + (lane & 7) + ((lane & 16) >> 1));
    const uint32_t b_coff = (uint32_t)((lane & 8) * 2);

    // per-thread load coords (2 rows of 4x8 cols)
    const int lr0 = tid >> 2, lc0 = tid & 3;          // u = tid
    const int lr1 = (tid + 256) >> 2;                 // u = tid + 256 (same lc)

    auto load_chunk = [&](int kc, int st) {
        const uint32_t sbs = sb0 + st * GP_STAGE;
        const uint32_t so0 = (uint32_t)(lr0 * GP_LDS + lc0 * 8) * 2;
        const uint32_t so1 = (uint32_t)(lr1 * GP_LDS + lc0 * 8) * 2;
        size_t ga0 = (size_t)(m0 + lr0) * D_ + kc * 32 + lc0 * 8;
        size_t ga1 = (size_t)(m0 + lr1) * D_ + kc * 32 + lc0 * 8;
        size_t gb0 = (size_t)(n0 + lr0) * D_ + kc * 32 + lc0 * 8;
        size_t gb1 = (size_t)(n0 + lr1) * D_ + kc * 32 + lc0 * 8;
        CP16(sbs + GP_AH + so0, Ahi + ga0);
        CP16(sbs + GP_AH + so1, Ahi + ga1);
        CP16(sbs + GP_AL + so0, Alo + ga0);
        CP16(sbs + GP_AL + so1, Alo + ga1);
        CP16(sbs + GP_BH + so0, Bhi + gb0);
        CP16(sbs + GP_BH + so1, Bhi + gb1);
        CP16(sbs + GP_BL + so0, Blo + gb0);
        CP16(sbs + GP_BL + so1, Blo + gb1);
    };

    load_chunk(0, 0);
    CP_COMMIT();

    for (int kc = 0; kc < 32; kc++) {
        const int cur = kc & 1;
        if (kc + 1 < 32) {
            load_chunk(kc + 1, cur ^ 1);
            CP_COMMIT();
            CP_WAIT1();
        } else {
            CP_WAIT0();
        }
        __syncthreads();

        const uint32_t sbs = sb0 + cur * GP_STAGE;
        const uint32_t s_ah = sbs + GP_AH, s_al = sbs + GP_AL;
        const uint32_t s_bh = sbs + GP_BH, s_bl = sbs + GP_BL;

        #pragma unroll
        for (int kk = 0; kk < 2; kk++) {
            const uint32_t kb = (uint32_t)(kk * 16 * 2);
            uint32_t bhf[2][4], blf[2][4];
            #pragma unroll
            for (int g = 0; g < 2; g++) {
                uint32_t ba = (b_row + g * 16) * (GP_LDS * 2) + kb + b_coff;
                LDM4(bhf[g], s_bh + ba);
                LDM4(blf[g], s_bl + ba);
            }
            #pragma unroll
            for (int mt = 0; mt < 4; mt++) {
                uint32_t aa = (a_row + mt * 16) * (GP_LDS * 2) + kb + a_coff;
                uint32_t ahf[4], alf[4];
                LDM4(ahf, s_ah + aa);
                LDM4(alf, s_al + aa);
                #pragma unroll
                for (int g = 0; g < 2; g++) {
                    #pragma unroll
                    for (int hf = 0; hf < 2; hf++) {
                        int nt = g * 2 + hf;
                        MMA_BF16(acc[mt][nt], ahf, bhf[g][hf*2], bhf[g][hf*2+1]);
                        MMA_BF16(acc[mt][nt], ahf, blf[g][hf*2], blf[g][hf*2+1]);
                        MMA_BF16(acc[mt][nt], alf, bhf[g][hf*2], bhf[g][hf*2+1]);
                    }
                }
            }
        }
        __syncthreads();
    }

    const int row0 = wm * 64 + (lane >> 2);
    const int col0 = wn * 32 + (lane & 3) * 2;
    #pragma unroll
    for (int mt = 0; mt < 4; mt++) {
        #pragma unroll
        for (int nt = 0; nt < 4; nt++) {
            #pragma unroll
            for (int r = 0; r < 4; r++) {
                int m = m0 + row0 + mt * 16 + (r >> 1) * 8;
                int j = n0 + col0 + nt * 8 + (r & 1);
                float val = acc[mt][nt][r] + bias[j];
                if (MODE == 1) {
                    oF[(size_t)m * D_ + j] = val;
                } else {
                    int b = m >> 11, n = m & (N_ - 1);
                    int h = j / E3_, e = j % E3_;
                    __nv_bfloat16 vh, vl; bf_split(val, vh, vl);
                    if (e < DH_) {
                        size_t o = ((size_t)(b * H_ + h) * N_ + n) * DH_ + e;
                        okh[o] = vh; okl[o] = vl;
                    } else if (e < 2 * DH_) {
                        size_t o = ((size_t)(b * H_ + h) * N_ + n) * DH_ + (e - DH_);
                        oqh[o] = vh; oql[o] = vl;
                    } else {
                        size_t o = ((size_t)(b * H_ + h) * DH_ + (e - 2 * DH_)) * N_ + n;
                        ovh[o] = vh; ovl[o] = vl;
                    }
                }
            }
        }
    }
}

// ---------------------------------------------------------------------------
// scores_mma (unchanged from R4): 128x128 tiles, kt <= qt, single K=64 shot.
// ---------------------------------------------------------------------------
#define SC_LDS 72
#define SC_TILE (128 * SC_LDS)
#define SC_AH 0
#define SC_AL (1 * SC_TILE)
#define SC_BH (2 * SC_TILE)
#define SC_BL (3 * SC_TILE)
#define SC_SMEM (4 * SC_TILE * 2)

__global__ __launch_bounds__(256) void scores_mma(
    const __nv_bfloat16* __restrict__ Qh, const __nv_bfloat16* __restrict__ Ql,
    const __nv_bfloat16* __restrict__ Kh, const __nv_bfloat16* __restrict__ Kl,
    float* __restrict__ attn)
{
    const int qt = blockIdx.x, kt = blockIdx.y, bh = blockIdx.z;
    if (kt > qt) return;

    extern __shared__ __nv_bfloat16 smem[];
    const int tid  = threadIdx.x;
    const int lane = tid & 31;
    const int wid  = tid >> 5;
    const int wm   = wid >> 2;
    const int wn   = wid & 3;

    const uint32_t s_ah = smem_u32(smem) + SC_AH * 2;
    const uint32_t s_al = smem_u32(smem) + SC_AL * 2;
    const uint32_t s_bh = smem_u32(smem) + SC_BH * 2;
    const uint32_t s_bl = smem_u32(smem) + SC_BL * 2;

    const __nv_bfloat16* qhb = Qh + ((size_t)bh * N_ + qt * 128) * DH_;
    const __nv_bfloat16* qlb = Ql + ((size_t)bh * N_ + qt * 128) * DH_;
    const __nv_bfloat16* khb = Kh + ((size_t)bh * N_ + kt * 128) * DH_;
    const __nv_bfloat16* klb = Kl + ((size_t)bh * N_ + kt * 128) * DH_;

    #pragma unroll
    for (int i = 0; i < 4; i++) {
        int u  = tid + i * 256;
        int r  = u >> 3, c8 = u & 7;
        int so = r * SC_LDS + c8 * 8;
        size_t g = (size_t)r * DH_ + c8 * 8;
        *(uint4*)(smem + SC_AH + so) = *(const uint4*)(qhb + g);
        *(uint4*)(smem + SC_AL + so) = *(const uint4*)(qlb + g);
        *(uint4*)(smem + SC_BH + so) = *(const uint4*)(khb + g);
        *(uint4*)(smem + SC_BL + so) = *(const uint4*)(klb + g);
    }
    __syncthreads();

    const uint32_t a_row  = (uint32_t)(wm * 64 + (lane & 15));
    const uint32_t a_coff = (uint32_t)(((lane >> 4) << 3) * 2);
    const uint32_t b_row  = (uint32_t)(wn * 32 + (lane & 7) + ((lane & 16) >> 1));
    const uint32_t b_coff = (uint32_t)((lane & 8) * 2);

    float acc[4][4][4] = {};
    #pragma unroll
    for (int kk = 0; kk < 4; kk++) {
        const uint32_t kb = (uint32_t)(kk * 16 * 2);
        uint32_t bhf[2][4], blf[2][4];
        #pragma unroll
        for (int g = 0; g < 2; g++) {
            uint32_t ba = (b_row + g * 16) * (SC_LDS * 2) + kb + b_coff;
            LDM4(bhf[g], s_bh + ba);
            LDM4(blf[g], s_bl + ba);
        }
        #pragma unroll
        for (int mt = 0; mt < 4; mt++) {
            uint32_t aa = (a_row + mt * 16) * (SC_LDS * 2) + kb + a_coff;
            uint32_t ahf[4], alf[4];
            LDM4(ahf, s_ah + aa);
            LDM4(alf, s_al + aa);
            #pragma unroll
            for (int g = 0; g < 2; g++) {
                #pragma unroll
                for (int hf = 0; hf < 2; hf++) {
                    int nt = g * 2 + hf;
                    MMA_BF16(acc[mt][nt], ahf, bhf[g][hf*2], bhf[g][hf*2+1]);
                    MMA_BF16(acc[mt][nt], ahf, blf[g][hf*2], blf[g][hf*2+1]);
                    MMA_BF16(acc[mt][nt], alf, bhf[g][hf*2], bhf[g][hf*2+1]);
                }
            }
        }
    }

    float* abase = attn + (size_t)bh * N_ * N_;
    const int row0 = wm * 64 + (lane >> 2);
    const int col0 = wn * 32 + (lane & 3) * 2;
    #pragma unroll
    for (int mt = 0; mt < 4; mt++) {
        #pragma unroll
        for (int nt = 0; nt < 4; nt++) {
            #pragma unroll
            for (int r = 0; r < 4; r++) {
                int qi = qt * 128 + row0 + mt * 16 + (r >> 1) * 8;
                int ki = kt * 128 + col0 + nt * 8 + (r & 1);
                abase[(size_t)qi * N_ + ki] = acc[mt][nt][r] * 0.125f;
            }
        }
    }
}

// ---------------------------------------------------------------------------
// softmax2 (unchanged from R4)
// ---------------------------------------------------------------------------
__global__ __launch_bounds__(256) void softmax2(
    float* __restrict__ attn,
    __nv_bfloat16* __restrict__ pbh, __nv_bfloat16* __restrict__ pbl)
{
    __shared__ float row[N_];
    __shared__ float red[256];

    const size_t r = blockIdx.x;
    const int qpos = blockIdx.x & (N_ - 1);
    const int kmax = ((qpos >> 7) + 1) << 7;
    float* s = attn + r * N_;
    __nv_bfloat16* ph = pbh + r * N_;
    __nv_bfloat16* pl = pbl + r * N_;
    const int tid = threadIdx.x;

    float m = -1e30f;
    for (int i = tid; i <= qpos; i += 256) {
        float v = s[i];
        row[i] = v;
        m = fmaxf(m, v);
    }
    red[tid] = m; __syncthreads();
    #pragma unroll
    for (int o = 128; o > 0; o >>= 1) {
        if (tid < o) red[tid] = fmaxf(red[tid], red[tid + o]);
        __syncthreads();
    }
    m = red[0]; __syncthreads();

    float sum = 0.f;
    for (int i = tid; i <= qpos; i += 256) {
        float e = __expf(row[i] - m);
        row[i] = e;
        sum += e;
    }
    red[tid] = sum; __syncthreads();
    #pragma unroll
    for (int o = 128; o > 0; o >>= 1) {
        if (tid < o) red[tid] += red[tid + o];
        __syncthreads();
    }
    const float inv = 1.0f / red[0];

    for (int i = tid; i < N_; i += 256) {
        float p = (i <= qpos) ? row[i] * inv : 0.f;
        s[i] = p;
        if (i < kmax) {
            __nv_bfloat16 h, l; bf_split(p, h, l);
            ph[i] = h; pl[i] = l;
        }
    }
}

// ---------------------------------------------------------------------------
// sa_pipe: sa = P @ V, 2-stage cp.async pipeline, flat K-chunks of 64.
// 8 warps (2x4), warp tile 64x16. Output bf16 hi/lo sa [B,N,D].
// Stage layout (bytes): PH=0(18432), PL=18432, VH=36864(9216), VL=46080;
// stage=55296; total 110,592 B.
// ---------------------------------------------------------------------------
#define SP_LDS 72
#define SP_PH 0
#define SP_PL 18432
#define SP_VH 36864
#define SP_VL 46080
#define SP_STAGE 55296
#define SP_SMEM (2 * SP_STAGE)          // 110,592 B

__global__ __launch_bounds__(256) void sa_pipe(
    const __nv_bfloat16* __restrict__ Ph, const __nv_bfloat16* __restrict__ Pl,
    const __nv_bfloat16* __restrict__ Vth, const __nv_bfloat16* __restrict__ Vtl,
    __nv_bfloat16* __restrict__ sahi, __nv_bfloat16* __restrict__ salo)
{
    extern __shared__ __nv_bfloat16 smem[];
    const uint32_t sb0 = smem_u32(smem);
    const int bh = blockIdx.x;
    const int qt = (N_ / 128 - 1) - blockIdx.y;    // heavy tiles first
    const int tid  = threadIdx.x;
    const int lane = tid & 31;
    const int wid  = tid >> 5;
    const int wm   = wid >> 2;
    const int wn   = wid & 3;

    const __nv_bfloat16* phb = Ph + ((size_t)bh * N_ + qt * 128) * N_;
    const __nv_bfloat16* plb = Pl + ((size_t)bh * N_ + qt * 128) * N_;
    const __nv_bfloat16* vhb = Vth + (size_t)bh * DH_ * N_;
    const __nv_bfloat16* vlb = Vtl + (size_t)bh * DH_ * N_;

    float acc[4][2][4] = {};

    const uint32_t a_row  = (uint32_t)(wm * 64 + (lane & 15));
    const uint32_t a_coff = (uint32_t)(((lane >> 4) << 3) * 2);
    const uint32_t b_row  = (uint32_t)(wn * 16 + (lane & 7) + ((lane & 16) >> 1));
    const uint32_t b_coff = (uint32_t)((lane & 8) * 2);

    const int lr = tid >> 3, lc = tid & 7;   // 32 rows per 256-thread pass, 8 cols

    auto load_chunk = [&](int kc, int st) {
        const uint32_t sbs = sb0 + st * SP_STAGE;
        const int kofs = kc * 64 + lc * 8;
        // P: 128 rows -> 4 passes
        #pragma unroll
        for (int i = 0; i < 4; i++) {
            int r = lr + i * 32;
            uint32_t so = (uint32_t)(r * SP_LDS + lc * 8) * 2;
            size_t g = (size_t)r * N_ + kofs;
            CP16(sbs + SP_PH + so, phb + g);
            CP16(sbs + SP_PL + so, plb + g);
        }
        // V: 64 rows -> 2 passes
        #pragma unroll
        for (int i = 0; i < 2; i++) {
            int r = lr + i * 32;
            uint32_t so = (uint32_t)(r * SP_LDS + lc * 8) * 2;
            size_t g = (size_t)r * N_ + kofs;
            CP16(sbs + SP_VH + so, vhb + g);
            CP16(sbs + SP_VL + so, vlb + g);
        }
    };

    const int nchunks = (qt + 1) * 2;
    load_chunk(0, 0);
    CP_COMMIT();

    for (int kc = 0; kc < nchunks; kc++) {
        const int cur = kc & 1;
        if (kc + 1 < nchunks) {
            load_chunk(kc + 1, cur ^ 1);
            CP_COMMIT();
            CP_WAIT1();
        } else {
            CP_WAIT0();
        }
        __syncthreads();

        const uint32_t sbs = sb0 + cur * SP_STAGE;
        const uint32_t s_ph = sbs + SP_PH, s_pl = sbs + SP_PL;
        const uint32_t s_vh = sbs + SP_VH, s_vl = sbs + SP_VL;

        #pragma unroll
        for (int kk = 0; kk < 4; kk++) {
            const uint32_t kb = (uint32_t)(kk * 16 * 2);
            uint32_t bhf[4], blf[4];
            uint32_t ba = b_row * (SP_LDS * 2) + kb + b_coff;
            LDM4(bhf, s_vh + ba);
            LDM4(blf, s_vl + ba);
            #pragma unroll
            for (int mt = 0; mt < 4; mt++) {
                uint32_t aa = (a_row + mt * 16) * (SP_LDS * 2) + kb + a_coff;
                uint32_t ahf[4], alf[4];
                LDM4(ahf, s_ph + aa);
                LDM4(alf, s_pl + aa);
                #pragma unroll
                for (int nt = 0; nt < 2; nt++) {
                    MMA_BF16(acc[mt][nt], ahf, bhf[nt*2], bhf[nt*2+1]);
                    MMA_BF16(acc[mt][nt], ahf, blf[nt*2], blf[nt*2+1]);
                    MMA_BF16(acc[mt][nt], alf, bhf[nt*2], bhf[nt*2+1]);
                }
            }
        }
        __syncthreads();
    }

    const int b = bh >> 4, h = bh & 15;
    const int row0 = wm * 64 + (lane >> 2);
    const int col0 = wn * 16 + (lane & 3) * 2;
    #pragma unroll
    for (int mt = 0; mt < 4; mt++) {
        #pragma unroll
        for (int nt = 0; nt < 2; nt++) {
            #pragma unroll
            for (int r = 0; r < 4; r++) {
                int n  = qt * 128 + row0 + mt * 16 + (r >> 1) * 8;
                int dh = col0 + nt * 8 + (r & 1);
                size_t o = ((size_t)b * N_ + n) * D_ + h * DH_ + dh;
                __nv_bfloat16 vh, vl; bf_split(acc[mt][nt][r], vh, vl);
                sahi[o] = vh; salo[o] = vl;
            }
        }
    }
}

// ---------------------------------------------------------------------------
extern "C" void kernel_launch(void* const* d_in, const int* in_sizes, int n_in,
                              void* d_out, int out_size)
{
    const float* x     = (const float*)d_in[0];
    const float* Wqkv  = (const float*)d_in[1];
    const float* bqkv  = (const float*)d_in[2];
    const float* Wproj = (const float*)d_in[3];
    const float* bproj = (const float*)d_in[4];
    float* out = (float*)d_out;

    const size_t OUT_ELEMS  = (size_t)B_ * N_ * D_;
    const size_t ATTN_ELEMS = (size_t)B_ * H_ * N_ * N_;

    float* attnp;
    cudaGetSymbolAddress((void**)&attnp, g_attn);
    if ((size_t)out_size >= OUT_ELEMS + ATTN_ELEMS)
        attnp = out + OUT_ELEMS;

    __nv_bfloat16 *xhi, *xlo, *wqhi, *wqlo, *wphi, *wplo, *sahi, *salo;
    __nv_bfloat16 *qh, *ql, *kh, *kl, *vth, *vtl, *pbh, *pbl;
    cudaGetSymbolAddress((void**)&xhi,  g_xhi);
    cudaGetSymbolAddress((void**)&xlo,  g_xlo);
    cudaGetSymbolAddress((void**)&wqhi, g_wqhi);
    cudaGetSymbolAddress((void**)&wqlo, g_wqlo);
    cudaGetSymbolAddress((void**)&wphi, g_wphi);
    cudaGetSymbolAddress((void**)&wplo, g_wplo);
    cudaGetSymbolAddress((void**)&sahi, g_sahi);
    cudaGetSymbolAddress((void**)&salo, g_salo);
    cudaGetSymbolAddress((void**)&qh,   g_qh);
    cudaGetSymbolAddress((void**)&ql,   g_ql);
    cudaGetSymbolAddress((void**)&kh,   g_kh);
    cudaGetSymbolAddress((void**)&kl,   g_kl);
    cudaGetSymbolAddress((void**)&vth,  g_vth);
    cudaGetSymbolAddress((void**)&vtl,  g_vtl);
    cudaGetSymbolAddress((void**)&pbh,  g_pbh);
    cudaGetSymbolAddress((void**)&pbl,  g_pbl);

    cudaFuncSetAttribute(gemm_pipe<0>, cudaFuncAttributeMaxDynamicSharedMemorySize, GP_SMEM);
    cudaFuncSetAttribute(gemm_pipe<1>, cudaFuncAttributeMaxDynamicSharedMemorySize, GP_SMEM);
    cudaFuncSetAttribute(scores_mma,   cudaFuncAttributeMaxDynamicSharedMemorySize, SC_SMEM);
    cudaFuncSetAttribute(sa_pipe,      cudaFuncAttributeMaxDynamicSharedMemorySize, SP_SMEM);

    split_kernel<<<(M_ * D_ + 255) / 256, 256>>>(x, xhi, xlo, M_ * D_);
    split_wqkv_kernel<<<(J3_ * D_ + 255) / 256, 256>>>(Wqkv, wqhi, wqlo);
    split_kernel<<<(D_ * D_ + 255) / 256, 256>>>(Wproj, wphi, wplo, D_ * D_);

    gemm_pipe<0><<<dim3(M_ / 128, J3_ / 128), 256, GP_SMEM>>>(
        xhi, xlo, wqhi, wqlo, bqkv, nullptr, kh, kl, qh, ql, vth, vtl);

    scores_mma<<<dim3(N_ / 128, N_ / 128, B_ * H_), 256, SC_SMEM>>>(
        qh, ql, kh, kl, attnp);

    softmax2<<<B_ * H_ * N_, 256>>>(attnp, pbh, pbl);

    sa_pipe<<<dim3(B_ * H_, N_ / 128), 256, SP_SMEM>>>(
        pbh, pbl, vth, vtl, sahi, salo);

    gemm_pipe<1><<<dim3(M_ / 128, D_ / 128), 256, GP_SMEM>>>(
        sahi, salo, wphi, wplo, bproj, out,
        nullptr, nullptr, nullptr, nullptr, nullptr, nullptr);
}